// round 3
// baseline (speedup 1.0000x reference)
#include <cuda_runtime.h>
#include <math.h>

#define BB 32
#define TT 256
#define INS 64
#define HH 128
#define G4 512
#define EPSV 1e-7f
#define NCACHE 14          // ulonglong2's of W_hh row cached in registers (56 regs)

typedef unsigned long long u64;

// ---- static device scratch (no cudaMalloc allowed) ----
__device__ __align__(16) u64 g_whp[32 * 512 * 2];   // W_hh packed: [k4][j] -> float4 as 2x u64
__device__ float g_gx[BB * TT * G4];                // precomputed input gate contributions

__device__ __forceinline__ u64 ffma2(u64 a, u64 b, u64 c) {
    u64 d;
    asm("fma.rn.f32x2 %0, %1, %2, %3;" : "=l"(d) : "l"(a), "l"(b), "l"(c));
    return d;
}
__device__ __forceinline__ float f2sum(u64 v) {
    float2 f = *reinterpret_cast<float2*>(&v);
    return f.x + f.y;
}
__device__ __forceinline__ float fsig(float x)  { return 1.0f / (1.0f + __expf(-x)); }
__device__ __forceinline__ float ftanh(float x) { return 2.0f / (1.0f + __expf(-2.0f * x)) - 1.0f; }

// ---------------- fused pack + gx kernel ----------------
__global__ __launch_bounds__(512) void gxpack_kernel(const float* __restrict__ x,
                                                     const float* __restrict__ W_ih,
                                                     const float* __restrict__ W_hh,
                                                     const float* __restrict__ b_ih,
                                                     const float* __restrict__ b_hh) {
    int b = blockIdx.x, ty = blockIdx.y, j = threadIdx.x;

    if (ty == 0) {
        float* whp = (float*)g_whp;
        for (int idx = b * 512 + j; idx < G4 * HH; idx += 32 * 512) {
            int r = idx >> 7, k = idx & 127;
            whp[((k >> 2) * 512 + r) * 4 + (k & 3)] = W_hh[idx];
        }
    }

    __shared__ float xs[16][INS];
    int t0 = ty * 16;
    for (int idx = j; idx < 16 * INS; idx += 512)
        xs[idx >> 6][idx & 63] = x[(b * TT + t0 + (idx >> 6)) * INS + (idx & 63)];

    float4 w[16];
    const float4* wr = (const float4*)(W_ih + j * INS);
#pragma unroll
    for (int k4 = 0; k4 < 16; k4++) w[k4] = wr[k4];
    float bs = b_ih[j] + b_hh[j];
    __syncthreads();

    for (int tt = 0; tt < 16; tt++) {
        float acc = bs;
#pragma unroll
        for (int k4 = 0; k4 < 16; k4++) {
            acc = fmaf(w[k4].x, xs[tt][4 * k4 + 0], acc);
            acc = fmaf(w[k4].y, xs[tt][4 * k4 + 1], acc);
            acc = fmaf(w[k4].z, xs[tt][4 * k4 + 2], acc);
            acc = fmaf(w[k4].w, xs[tt][4 * k4 + 3], acc);
        }
        g_gx[(b * TT + t0 + tt) * G4 + j] = acc;
    }
}

// ---------------- recurrent kernel: one block per batch row ----------------
__global__ __launch_bounds__(512) void rec_kernel(const float* __restrict__ w_t,
                                                  float* __restrict__ out) {
    int b = blockIdx.x, tid = threadIdx.x, lane = tid & 31, wrp = tid >> 5;

    __shared__ __align__(16) float h_sh[HH];
    __shared__ float g_sh[G4];
    __shared__ __align__(16) float slots[5][HH];   // h rows for running top-5
    __shared__ float redA[4], redB[4];
    __shared__ float sb_arr[TT];
    __shared__ float top5v[5];
    __shared__ int   top5r[5];
    __shared__ int   top5s[5];
    __shared__ int   rowslot[5];                   // row r (r<5) -> slot
    __shared__ int   evslot;
    __shared__ float wa_s[HH], wb_s[HH];

    float* out_c = out;             // [B,H]
    float* out_w = out + BB * HH;   // [B,T]
    const float* gxb = g_gx + b * TT * G4;

    if (tid < HH) {
        h_sh[tid] = 0.0f;
        slots[0][tid] = 0.0f;       // row 0 = zeros
        wa_s[tid] = w_t[tid];
        wb_s[tid] = w_t[HH + tid];
    }
    if (tid == 0) {
        sb_arr[0] = 0.0f;
        top5v[0] = 0.0f; top5r[0] = 0; top5s[0] = 0;
        for (int q = 1; q < 5; q++) { top5v[q] = -1e30f; top5r[q] = -1; top5s[q] = q; }
        rowslot[0] = 0;
        evslot = -1;
        redB[0] = redB[1] = redB[2] = redB[3] = 0.0f;
    }
    if (tid < TT) out_w[b * TT + tid] = 0.0f;

    float c_reg = 0.0f;
    float ac = 0.0f;

    // cache first NCACHE ulonglong2 (k=0..4*NCACHE-1) of this row; stream the rest from L1
    const ulonglong2* wp = (const ulonglong2*)g_whp;
    ulonglong2 wc[NCACHE];
#pragma unroll
    for (int k4 = 0; k4 < NCACHE; k4++) wc[k4] = wp[k4 * 512 + tid];

    __syncthreads();

    for (int i = 0; i < TT; i++) {
        float gxv = gxb[i * G4 + tid];

        // ---- phase A: top-5 maintenance for row i (thread 0, overlaps other warps' GEMV) ----
        if (tid == 0 && i > 0) {
            float sbn = redB[0] + redB[1] + redB[2] + redB[3];
            sb_arr[i] = sbn;
            if (sbn > top5v[4]) {
                int evs = top5s[4];
                int p = 4;
                while (p > 0 && sbn > top5v[p - 1]) {
                    top5v[p] = top5v[p - 1]; top5r[p] = top5r[p - 1]; top5s[p] = top5s[p - 1];
                    p--;
                }
                top5v[p] = sbn; top5r[p] = i; top5s[p] = evs;
                if (i < 5) rowslot[i] = evs;
                evslot = evs;
            } else evslot = -1;
        }

        // ---- GEMV with packed f32x2 FMA ----
        const ulonglong2* h2 = (const ulonglong2*)h_sh;
        u64 a0 = 0ull, a1 = 0ull, a2 = 0ull, a3 = 0ull;
#pragma unroll
        for (int k4 = 0; k4 < NCACHE; k4++) {
            ulonglong2 w = wc[k4];
            ulonglong2 hv = h2[k4];
            if (k4 & 1) { a2 = ffma2(w.x, hv.x, a2); a3 = ffma2(w.y, hv.y, a3); }
            else        { a0 = ffma2(w.x, hv.x, a0); a1 = ffma2(w.y, hv.y, a1); }
        }
#pragma unroll
        for (int k4 = NCACHE; k4 < 32; k4++) {
            ulonglong2 w = wp[k4 * 512 + tid];
            ulonglong2 hv = h2[k4];
            if (k4 & 1) { a2 = ffma2(w.x, hv.x, a2); a3 = ffma2(w.y, hv.y, a3); }
            else        { a0 = ffma2(w.x, hv.x, a0); a1 = ffma2(w.y, hv.y, a1); }
        }
        float g = gxv + ((f2sum(a0) + f2sum(a1)) + (f2sum(a2) + f2sum(a3)));
        g_sh[tid] = ((tid >> 7) == 2) ? ftanh(g) : fsig(g);
        __syncthreads();  // B1

        // ---- phase B: slot copy + LSTM cell + ta partials (threads 0..127) ----
        float hl = 0.0f;
        if (tid < HH) {
            int ev = evslot;
            if (ev >= 0) slots[ev][tid] = h_sh[tid];   // insert row i (prev step's h)
            float ti = g_sh[tid], tf = g_sh[HH + tid];
            float tg = g_sh[2 * HH + tid], to = g_sh[3 * HH + tid];
            c_reg = tf * c_reg + ti * tg;
            hl = to * ftanh(c_reg);
            float pa = ftanh(hl) * wa_s[tid];
#pragma unroll
            for (int o = 16; o; o >>= 1) pa += __shfl_xor_sync(0xffffffffu, pa, o);
            if (lane == 0) redA[wrp] = pa;
        }
        __syncthreads();  // B2

        // ---- phase C: sparse attention (redundant on 128 threads), h update, sb partials ----
        if (tid < HH) {
            float ta = redA[0] + redA[1] + redA[2] + redA[3];
            int rem = i + 1;
            float wv[5]; int ws[5];
            if (rem <= 5) {
#pragma unroll
                for (int r = 0; r < 5; r++) {
                    if (r < rem) { wv[r] = ta + sb_arr[r]; ws[r] = rowslot[r]; }
                    else         { wv[r] = 0.0f;           ws[r] = 0; }
                }
            } else {
                float d = top5v[4] + EPSV;
                float ssum = 0.0f;
#pragma unroll
                for (int q = 0; q < 5; q++) {
                    float v = fmaxf(top5v[q] - d, 0.0f);
                    wv[q] = v; ws[q] = top5s[q];
                    ssum += v;
                }
                float inv = 1.0f / (ssum + EPSV);
#pragma unroll
                for (int q = 0; q < 5; q++) wv[q] *= inv;
            }
            ac = 0.0f;
#pragma unroll
            for (int q = 0; q < 5; q++) ac = fmaf(wv[q], slots[ws[q]][tid], ac);
            float hf = hl + ac;
            h_sh[tid] = hf;
            float pb = ftanh(hf) * wb_s[tid];
#pragma unroll
            for (int o = 16; o; o >>= 1) pb += __shfl_xor_sync(0xffffffffu, pb, o);
            if (lane == 0) redB[wrp] = pb;
        }
        __syncthreads();  // B3 (end of step)
    }

    // ---- epilogue: write last-step outputs ----
    if (tid < HH) out_c[b * HH + tid] = ac;
    if (tid == 0) {
        // last step had rem=256>5: normalized sparse weights from the running top-5
        float d = top5v[4] + EPSV;
        float ssum = 0.0f, v[5];
#pragma unroll
        for (int q = 0; q < 5; q++) { v[q] = fmaxf(top5v[q] - d, 0.0f); ssum += v[q]; }
        float inv = 1.0f / (ssum + EPSV);
#pragma unroll
        for (int q = 0; q < 5; q++)
            if (v[q] > 0.0f) out_w[b * TT + top5r[q]] = v[q] * inv;
    }
}

extern "C" void kernel_launch(void* const* d_in, const int* in_sizes, int n_in,
                              void* d_out, int out_size) {
    const float* x    = (const float*)d_in[0];
    const float* W_ih = (const float*)d_in[1];
    const float* W_hh = (const float*)d_in[2];
    const float* b_ih = (const float*)d_in[3];
    const float* b_hh = (const float*)d_in[4];
    const float* w_t  = (const float*)d_in[5];
    float* out = (float*)d_out;

    gxpack_kernel<<<dim3(BB, TT / 16), 512>>>(x, W_ih, W_hh, b_ih, b_hh);
    rec_kernel<<<BB, 512>>>(w_t, out);
}

// round 4
// speedup vs baseline: 1.0524x; 1.0524x over previous
#include <cuda_runtime.h>
#include <math.h>

#define BB 32
#define TT 256
#define INS 64
#define HH 128
#define G4 512
#define EPSV 1e-7f
#define NCACHE 16          // ulonglong2's of W_hh row cached in registers (64 regs)

typedef unsigned long long u64;

// ---- static device scratch (no cudaMalloc allowed) ----
__device__ __align__(16) u64 g_whp[32 * 512 * 2];   // W_hh packed: [k4][j] -> float4 as 2x u64
__device__ float g_gx[BB * TT * G4];                // precomputed input gate contributions

__device__ __forceinline__ u64 ffma2(u64 a, u64 b, u64 c) {
    u64 d;
    asm("fma.rn.f32x2 %0, %1, %2, %3;" : "=l"(d) : "l"(a), "l"(b), "l"(c));
    return d;
}
__device__ __forceinline__ float f2sum(u64 v) {
    float2 f = *reinterpret_cast<float2*>(&v);
    return f.x + f.y;
}
__device__ __forceinline__ float fsig(float x)  { return 1.0f / (1.0f + __expf(-x)); }
__device__ __forceinline__ float ftanh(float x) { return 2.0f / (1.0f + __expf(-2.0f * x)) - 1.0f; }

// ---------------- fused pack + gx kernel ----------------
__global__ __launch_bounds__(512) void gxpack_kernel(const float* __restrict__ x,
                                                     const float* __restrict__ W_ih,
                                                     const float* __restrict__ W_hh,
                                                     const float* __restrict__ b_ih,
                                                     const float* __restrict__ b_hh) {
    int b = blockIdx.x, ty = blockIdx.y, j = threadIdx.x;

    if (ty == 0) {
        float* whp = (float*)g_whp;
        for (int idx = b * 512 + j; idx < G4 * HH; idx += 32 * 512) {
            int r = idx >> 7, k = idx & 127;
            whp[((k >> 2) * 512 + r) * 4 + (k & 3)] = W_hh[idx];
        }
    }

    __shared__ float xs[16][INS];
    int t0 = ty * 16;
    for (int idx = j; idx < 16 * INS; idx += 512)
        xs[idx >> 6][idx & 63] = x[(b * TT + t0 + (idx >> 6)) * INS + (idx & 63)];

    float4 w[16];
    const float4* wr = (const float4*)(W_ih + j * INS);
#pragma unroll
    for (int k4 = 0; k4 < 16; k4++) w[k4] = wr[k4];
    float bs = b_ih[j] + b_hh[j];
    __syncthreads();

    for (int tt = 0; tt < 16; tt++) {
        float acc = bs;
#pragma unroll
        for (int k4 = 0; k4 < 16; k4++) {
            acc = fmaf(w[k4].x, xs[tt][4 * k4 + 0], acc);
            acc = fmaf(w[k4].y, xs[tt][4 * k4 + 1], acc);
            acc = fmaf(w[k4].z, xs[tt][4 * k4 + 2], acc);
            acc = fmaf(w[k4].w, xs[tt][4 * k4 + 3], acc);
        }
        g_gx[(b * TT + t0 + tt) * G4 + j] = acc;
    }
}

// ---------------- recurrent kernel: one block per batch row ----------------
__global__ __launch_bounds__(512) void rec_kernel(const float* __restrict__ w_t,
                                                  float* __restrict__ out) {
    int b = blockIdx.x, tid = threadIdx.x, lane = tid & 31, wrp = tid >> 5;

    __shared__ __align__(16) float h_sh[HH];
    __shared__ float g_sh[G4];
    __shared__ __align__(16) float slots[5][HH];   // h rows for running top-5
    __shared__ float redA[4], redB[4];
    __shared__ float sb_arr[TT];
    __shared__ float top5v[5];
    __shared__ int   top5r[5];
    __shared__ int   top5s[5];
    __shared__ int   rowslot[5];                   // row r (r<5) -> slot
    __shared__ int   evslot;
    __shared__ float wa_s[HH], wb_s[HH];

    float* out_c = out;             // [B,H]
    float* out_w = out + BB * HH;   // [B,T]
    const float* gxb = g_gx + b * TT * G4;

    if (tid < HH) {
        h_sh[tid] = 0.0f;
        slots[0][tid] = 0.0f;       // row 0 = zeros
        wa_s[tid] = w_t[tid];
        wb_s[tid] = w_t[HH + tid];
    }
    if (tid == 0) {
        sb_arr[0] = 0.0f;
        top5v[0] = 0.0f; top5r[0] = 0; top5s[0] = 0;
        for (int q = 1; q < 5; q++) { top5v[q] = -1e30f; top5r[q] = -1; top5s[q] = q; }
        rowslot[0] = 0;
        evslot = -1;
        redB[0] = redB[1] = redB[2] = redB[3] = 0.0f;
    }
    if (tid < TT) out_w[b * TT + tid] = 0.0f;

    float c_reg = 0.0f;
    float ac = 0.0f;

    // cache first NCACHE ulonglong2 of this row; stream the rest from L1
    const ulonglong2* wp = (const ulonglong2*)g_whp;
    ulonglong2 wc[NCACHE];
#pragma unroll
    for (int k4 = 0; k4 < NCACHE; k4++) wc[k4] = wp[k4 * 512 + tid];

    __syncthreads();

    // software-pipelined gx load: gx for step i is loaded during step i-1
    float gx_cur = gxb[tid];

    for (int i = 0; i < TT; i++) {
        // prefetch next step's gx (consumed next iteration -> full step of latency hiding)
        float gx_next = 0.0f;
        if (i + 1 < TT) gx_next = gxb[(i + 1) * G4 + tid];

        // ---- phase A: top-5 maintenance for row i (tid 128 = warp 4; overlaps
        //      warps 0-3's GEMV which feeds the tail phases) ----
        if (tid == 128 && i > 0) {
            float sbn = redB[0] + redB[1] + redB[2] + redB[3];
            sb_arr[i] = sbn;
            if (sbn > top5v[4]) {
                int evs = top5s[4];
                int p = 4;
                while (p > 0 && sbn > top5v[p - 1]) {
                    top5v[p] = top5v[p - 1]; top5r[p] = top5r[p - 1]; top5s[p] = top5s[p - 1];
                    p--;
                }
                top5v[p] = sbn; top5r[p] = i; top5s[p] = evs;
                if (i < 5) rowslot[i] = evs;
                evslot = evs;
            } else evslot = -1;
        }

        // ---- GEMV with packed f32x2 FMA ----
        const ulonglong2* h2 = (const ulonglong2*)h_sh;
        u64 a0 = 0ull, a1 = 0ull, a2 = 0ull, a3 = 0ull;
#pragma unroll
        for (int k4 = 0; k4 < NCACHE; k4++) {
            ulonglong2 w = wc[k4];
            ulonglong2 hv = h2[k4];
            if (k4 & 1) { a2 = ffma2(w.x, hv.x, a2); a3 = ffma2(w.y, hv.y, a3); }
            else        { a0 = ffma2(w.x, hv.x, a0); a1 = ffma2(w.y, hv.y, a1); }
        }
#pragma unroll
        for (int k4 = NCACHE; k4 < 32; k4++) {
            ulonglong2 w = wp[k4 * 512 + tid];
            ulonglong2 hv = h2[k4];
            if (k4 & 1) { a2 = ffma2(w.x, hv.x, a2); a3 = ffma2(w.y, hv.y, a3); }
            else        { a0 = ffma2(w.x, hv.x, a0); a1 = ffma2(w.y, hv.y, a1); }
        }
        float g = gx_cur + ((f2sum(a0) + f2sum(a1)) + (f2sum(a2) + f2sum(a3)));
        g_sh[tid] = ((tid >> 7) == 2) ? ftanh(g) : fsig(g);
        gx_cur = gx_next;
        __syncthreads();  // B1

        // ---- tail phases: only warps 0-3; others proceed to B3 and wait ----
        if (tid < HH) {
            // phase B: slot copy + LSTM cell + ta partials
            int ev = evslot;
            if (ev >= 0) slots[ev][tid] = h_sh[tid];   // insert row i (prev step's h)
            float ti = g_sh[tid], tf = g_sh[HH + tid];
            float tg = g_sh[2 * HH + tid], to = g_sh[3 * HH + tid];
            c_reg = tf * c_reg + ti * tg;
            float hl = to * ftanh(c_reg);
            float pa = ftanh(hl) * wa_s[tid];
#pragma unroll
            for (int o = 16; o; o >>= 1) pa += __shfl_xor_sync(0xffffffffu, pa, o);
            if (lane == 0) redA[wrp] = pa;
            asm volatile("bar.sync 1, 128;" ::: "memory");   // B2: warps 0-3 only

            // phase C: sparse attention (redundant on 128 threads), h update, sb partials
            float ta = redA[0] + redA[1] + redA[2] + redA[3];
            int rem = i + 1;
            float wv[5]; int ws[5];
            if (rem <= 5) {
#pragma unroll
                for (int r = 0; r < 5; r++) {
                    if (r < rem) { wv[r] = ta + sb_arr[r]; ws[r] = rowslot[r]; }
                    else         { wv[r] = 0.0f;           ws[r] = 0; }
                }
            } else {
                float d = top5v[4] + EPSV;
                float ssum = 0.0f;
#pragma unroll
                for (int q = 0; q < 5; q++) {
                    float v = fmaxf(top5v[q] - d, 0.0f);
                    wv[q] = v; ws[q] = top5s[q];
                    ssum += v;
                }
                float inv = 1.0f / (ssum + EPSV);
#pragma unroll
                for (int q = 0; q < 5; q++) wv[q] *= inv;
            }
            ac = 0.0f;
#pragma unroll
            for (int q = 0; q < 5; q++) ac = fmaf(wv[q], slots[ws[q]][tid], ac);
            float hf = hl + ac;
            h_sh[tid] = hf;
            float pb = ftanh(hf) * wb_s[tid];
#pragma unroll
            for (int o = 16; o; o >>= 1) pb += __shfl_xor_sync(0xffffffffu, pb, o);
            if (lane == 0) redB[wrp] = pb;
        }
        __syncthreads();  // B3 (end of step)
    }

    // ---- epilogue: write last-step outputs ----
    if (tid < HH) out_c[b * HH + tid] = ac;
    if (tid == 0) {
        // last step had rem=256>5: normalized sparse weights from the running top-5
        float d = top5v[4] + EPSV;
        float ssum = 0.0f, v[5];
#pragma unroll
        for (int q = 0; q < 5; q++) { v[q] = fmaxf(top5v[q] - d, 0.0f); ssum += v[q]; }
        float inv = 1.0f / (ssum + EPSV);
#pragma unroll
        for (int q = 0; q < 5; q++)
            if (v[q] > 0.0f) out_w[b * TT + top5r[q]] = v[q] * inv;
    }
}

extern "C" void kernel_launch(void* const* d_in, const int* in_sizes, int n_in,
                              void* d_out, int out_size) {
    const float* x    = (const float*)d_in[0];
    const float* W_ih = (const float*)d_in[1];
    const float* W_hh = (const float*)d_in[2];
    const float* b_ih = (const float*)d_in[3];
    const float* b_hh = (const float*)d_in[4];
    const float* w_t  = (const float*)d_in[5];
    float* out = (float*)d_out;

    gxpack_kernel<<<dim3(BB, TT / 16), 512>>>(x, W_ih, W_hh, b_ih, b_hh);
    rec_kernel<<<BB, 512>>>(w_t, out);
}

// round 6
// speedup vs baseline: 1.2221x; 1.1612x over previous
#include <cuda_runtime.h>
#include <stdint.h>
#include <math.h>

#define BB 32
#define TT 256
#define INS 64
#define HH 128
#define G4 512
#define EPSV 1e-7f

typedef unsigned long long u64;
typedef unsigned int u32;

// ---- static device scratch (no cudaMalloc allowed) ----
__device__ __align__(16) u64 g_whp[32 * 512 * 2];   // W_hh packed: [k4][j] -> float4 as 2x u64
__device__ float g_gx[BB * TT * G4];                // precomputed input gate contributions

__device__ __forceinline__ u64 ffma2(u64 a, u64 b, u64 c) {
    u64 d;
    asm("fma.rn.f32x2 %0, %1, %2, %3;" : "=l"(d) : "l"(a), "l"(b), "l"(c));
    return d;
}
__device__ __forceinline__ float f2sum(u64 v) {
    float2 f = *reinterpret_cast<float2*>(&v);
    return f.x + f.y;
}
__device__ __forceinline__ float fsig(float x)  { return 1.0f / (1.0f + __expf(-x)); }
__device__ __forceinline__ float ftanh(float x) { return 2.0f / (1.0f + __expf(-2.0f * x)) - 1.0f; }

__device__ __forceinline__ u32 smem_u32(const void* p) {
    u32 a;
    asm("{ .reg .u64 t; cvta.to.shared.u64 t, %1; cvt.u32.u64 %0, t; }" : "=r"(a) : "l"(p));
    return a;
}

// ---------------- fused pack + gx kernel ----------------
__global__ __launch_bounds__(512) void gxpack_kernel(const float* __restrict__ x,
                                                     const float* __restrict__ W_ih,
                                                     const float* __restrict__ W_hh,
                                                     const float* __restrict__ b_ih,
                                                     const float* __restrict__ b_hh) {
    int b = blockIdx.x, ty = blockIdx.y, j = threadIdx.x;

    if (ty == 0) {
        float* whp = (float*)g_whp;
        for (int idx = b * 512 + j; idx < G4 * HH; idx += 32 * 512) {
            int r = idx >> 7, k = idx & 127;
            whp[((k >> 2) * 512 + r) * 4 + (k & 3)] = W_hh[idx];
        }
    }

    __shared__ float xs[16][INS];
    int t0 = ty * 16;
    for (int idx = j; idx < 16 * INS; idx += 512)
        xs[idx >> 6][idx & 63] = x[(b * TT + t0 + (idx >> 6)) * INS + (idx & 63)];

    float4 w[16];
    const float4* wr = (const float4*)(W_ih + j * INS);
#pragma unroll
    for (int k4 = 0; k4 < 16; k4++) w[k4] = wr[k4];
    float bs = b_ih[j] + b_hh[j];
    __syncthreads();

    for (int tt = 0; tt < 16; tt++) {
        float acc = bs;
#pragma unroll
        for (int k4 = 0; k4 < 16; k4++) {
            acc = fmaf(w[k4].x, xs[tt][4 * k4 + 0], acc);
            acc = fmaf(w[k4].y, xs[tt][4 * k4 + 1], acc);
            acc = fmaf(w[k4].z, xs[tt][4 * k4 + 2], acc);
            acc = fmaf(w[k4].w, xs[tt][4 * k4 + 3], acc);
        }
        g_gx[(b * TT + t0 + tt) * G4 + j] = acc;
    }
}

// ---------------- recurrent kernel: cluster of 2 CTAs per batch row ----------------
// CTA rank r handles k-half r of the 512x128 GEMV; W_hh half lives fully in registers.
__global__ __launch_bounds__(512) void rec_kernel(const float* __restrict__ w_t,
                                                  float* __restrict__ out) {
    int tid = threadIdx.x, lane = tid & 31, wrp = tid >> 5;
    int b = blockIdx.x >> 1;

    u32 rank;
    asm("mov.u32 %0, %%cluster_ctarank;" : "=r"(rank));
    u32 peer = rank ^ 1u;

    __shared__ __align__(16) float h_sh[HH];
    __shared__ float gpart[2][2][G4];              // [parity][khalf][gate]
    __shared__ __align__(16) float slots[5][HH];   // h rows for running top-5
    __shared__ float redA[4], redB[4];
    __shared__ float sb_arr[8];                    // only rows 0..4 ever read
    __shared__ float top5v[5];
    __shared__ int   top5r[5];
    __shared__ int   top5s[5];
    __shared__ int   rowslot[5];
    __shared__ int   evslot;
    __shared__ float wa_s[HH], wb_s[HH];

    float* out_c = out;             // [B,H]
    float* out_w = out + BB * HH;   // [B,T]
    const float* gxb = g_gx + b * TT * G4;

    if (tid < HH) {
        h_sh[tid] = 0.0f;
        slots[0][tid] = 0.0f;
        wa_s[tid] = w_t[tid];
        wb_s[tid] = w_t[HH + tid];
    }
    if (tid == 0) {
        sb_arr[0] = 0.0f;
        top5v[0] = 0.0f; top5r[0] = 0; top5s[0] = 0;
        for (int q = 1; q < 5; q++) { top5v[q] = -1e30f; top5r[q] = -1; top5s[q] = q; }
        rowslot[0] = 0;
        evslot = -1;
        redB[0] = redB[1] = redB[2] = redB[3] = 0.0f;
    }
    if (rank == 0 && tid < TT) out_w[b * TT + tid] = 0.0f;

    // remote addresses of peer's gpart[p][rank][0]
    u32 gl0 = smem_u32(&gpart[0][rank][0]);
    u32 gl1 = smem_u32(&gpart[1][rank][0]);
    u32 gr0, gr1;
    asm("mapa.shared::cluster.u32 %0, %1, %2;" : "=r"(gr0) : "r"(gl0), "r"(peer));
    asm("mapa.shared::cluster.u32 %0, %1, %2;" : "=r"(gr1) : "r"(gl1), "r"(peer));

    float c_reg = 0.0f;
    float ac = 0.0f;

    // this CTA's W_hh half: rows = gate j (tid), cols = k in [rank*64, rank*64+64)
    const ulonglong2* wp = (const ulonglong2*)g_whp;
    ulonglong2 wc[16];
#pragma unroll
    for (int k4 = 0; k4 < 16; k4++) wc[k4] = wp[(rank * 16 + k4) * 512 + tid];

    __syncthreads();
    // ensure both CTAs initialized before any remote traffic
    asm volatile("barrier.cluster.arrive.aligned;" ::: "memory");
    asm volatile("barrier.cluster.wait.aligned;"   ::: "memory");

    // gx prefetch: only tail threads (tid<128) need gx, 4 gate rows each
    float gx0 = 0.f, gx1 = 0.f, gx2 = 0.f, gx3 = 0.f;
    if (tid < HH) {
        gx0 = gxb[tid];
        gx1 = gxb[HH + tid];
        gx2 = gxb[2 * HH + tid];
        gx3 = gxb[3 * HH + tid];
    }

    for (int i = 0; i < TT; i++) {
        int p = i & 1;

        // ---- phase A: top-5 maintenance for row i (tid 128 = warp 4, overlaps GEMV) ----
        if (tid == 128 && i > 0) {
            float sbn = redB[0] + redB[1] + redB[2] + redB[3];
            if (i < 5) sb_arr[i] = sbn;
            if (sbn > top5v[4]) {
                int evs = top5s[4];
                int q = 4;
                while (q > 0 && sbn > top5v[q - 1]) {
                    top5v[q] = top5v[q - 1]; top5r[q] = top5r[q - 1]; top5s[q] = top5s[q - 1];
                    q--;
                }
                top5v[q] = sbn; top5r[q] = i; top5s[q] = evs;
                if (i < 5) rowslot[i] = evs;
                evslot = evs;
            } else evslot = -1;
        }

        // ---- GEMV half: partial[tid] = sum over this CTA's 64 k's, all from registers ----
        const ulonglong2* h2 = (const ulonglong2*)h_sh;
        u64 a0 = 0ull, a1 = 0ull, a2 = 0ull, a3 = 0ull;
#pragma unroll
        for (int k4 = 0; k4 < 16; k4++) {
            ulonglong2 w = wc[k4];
            ulonglong2 hv = h2[rank * 16 + k4];
            if (k4 & 1) { a2 = ffma2(w.x, hv.x, a2); a3 = ffma2(w.y, hv.y, a3); }
            else        { a0 = ffma2(w.x, hv.x, a0); a1 = ffma2(w.y, hv.y, a1); }
        }
        float part = (f2sum(a0) + f2sum(a1)) + (f2sum(a2) + f2sum(a3));

        gpart[p][rank][tid] = part;                      // local copy
        u32 ra = (p ? gr1 : gr0) + tid * 4u;             // peer copy (DSMEM)
        asm volatile("st.shared::cluster.f32 [%0], %1;" :: "r"(ra), "f"(part) : "memory");

        // one cluster barrier per step: partials complete + CTA-wide sync
        asm volatile("barrier.cluster.arrive.aligned;" ::: "memory");
        asm volatile("barrier.cluster.wait.aligned;"   ::: "memory");

        // ---- tail: warps 0-3 only (redundant in both CTAs) ----
        if (tid < HH) {
            // combine partials + gx, apply nonlinearities
            float ti = fsig (gpart[p][0][tid]            + gpart[p][1][tid]            + gx0);
            float tf = fsig (gpart[p][0][HH + tid]       + gpart[p][1][HH + tid]       + gx1);
            float tg = ftanh(gpart[p][0][2 * HH + tid]   + gpart[p][1][2 * HH + tid]   + gx2);
            float to = fsig (gpart[p][0][3 * HH + tid]   + gpart[p][1][3 * HH + tid]   + gx3);

            // prefetch next step's gx (hidden behind next GEMV + sync)
            if (i + 1 < TT) {
                const float* gn = gxb + (i + 1) * G4;
                gx0 = gn[tid]; gx1 = gn[HH + tid]; gx2 = gn[2 * HH + tid]; gx3 = gn[3 * HH + tid];
            }

            // slot copy (previous h) + LSTM cell + ta partials
            int ev = evslot;
            if (ev >= 0) slots[ev][tid] = h_sh[tid];
            c_reg = tf * c_reg + ti * tg;
            float hl = to * ftanh(c_reg);
            float pa = ftanh(hl) * wa_s[tid];
#pragma unroll
            for (int o = 16; o; o >>= 1) pa += __shfl_xor_sync(0xffffffffu, pa, o);
            if (lane == 0) redA[wrp] = pa;
            asm volatile("bar.sync 1, 128;" ::: "memory");   // B2: warps 0-3 only

            // sparse attention (redundant on 128 threads), h update, sb partials
            float ta = redA[0] + redA[1] + redA[2] + redA[3];
            int rem = i + 1;
            float wv[5]; int ws[5];
            if (rem <= 5) {
#pragma unroll
                for (int r = 0; r < 5; r++) {
                    if (r < rem) { wv[r] = ta + sb_arr[r]; ws[r] = rowslot[r]; }
                    else         { wv[r] = 0.0f;           ws[r] = 0; }
                }
            } else {
                float d = top5v[4] + EPSV;
                float ssum = 0.0f;
#pragma unroll
                for (int q = 0; q < 5; q++) {
                    float v = fmaxf(top5v[q] - d, 0.0f);
                    wv[q] = v; ws[q] = top5s[q];
                    ssum += v;
                }
                float inv = 1.0f / (ssum + EPSV);
#pragma unroll
                for (int q = 0; q < 5; q++) wv[q] *= inv;
            }
            ac = 0.0f;
#pragma unroll
            for (int q = 0; q < 5; q++) ac = fmaf(wv[q], slots[ws[q]][tid], ac);
            float hf = hl + ac;
            h_sh[tid] = hf;
            float pb = ftanh(hf) * wb_s[tid];
#pragma unroll
            for (int o = 16; o; o >>= 1) pb += __shfl_xor_sync(0xffffffffu, pb, o);
            if (lane == 0) redB[wrp] = pb;
        }
        __syncthreads();  // B3: h_sh stable before next GEMV; redB before next phase A
    }

    // ---- epilogue (rank 0 only) ----
    if (rank == 0) {
        if (tid < HH) out_c[b * HH + tid] = ac;
        if (tid == 0) {
            float d = top5v[4] + EPSV;
            float ssum = 0.0f, v[5];
#pragma unroll
            for (int q = 0; q < 5; q++) { v[q] = fmaxf(top5v[q] - d, 0.0f); ssum += v[q]; }
            float inv = 1.0f / (ssum + EPSV);
#pragma unroll
            for (int q = 0; q < 5; q++)
                if (v[q] > 0.0f) out_w[b * TT + top5r[q]] = v[q] * inv;
        }
    }
    // final cluster barrier: no CTA exits while peer may still be targeted
    asm volatile("barrier.cluster.arrive.aligned;" ::: "memory");
    asm volatile("barrier.cluster.wait.aligned;"   ::: "memory");
}

extern "C" void kernel_launch(void* const* d_in, const int* in_sizes, int n_in,
                              void* d_out, int out_size) {
    const float* x    = (const float*)d_in[0];
    const float* W_ih = (const float*)d_in[1];
    const float* W_hh = (const float*)d_in[2];
    const float* b_ih = (const float*)d_in[3];
    const float* b_hh = (const float*)d_in[4];
    const float* w_t  = (const float*)d_in[5];
    float* out = (float*)d_out;

    gxpack_kernel<<<dim3(BB, TT / 16), 512>>>(x, W_ih, W_hh, b_ih, b_hh);

    cudaLaunchConfig_t cfg = {};
    cfg.gridDim  = dim3(2 * BB, 1, 1);
    cfg.blockDim = dim3(512, 1, 1);
    cfg.dynamicSmemBytes = 0;
    cfg.stream = 0;
    cudaLaunchAttribute attrs[1];
    attrs[0].id = cudaLaunchAttributeClusterDimension;
    attrs[0].val.clusterDim.x = 2;
    attrs[0].val.clusterDim.y = 1;
    attrs[0].val.clusterDim.z = 1;
    cfg.attrs = attrs;
    cfg.numAttrs = 1;
    cudaLaunchKernelEx(&cfg, rec_kernel, w_t, out);
}

// round 7
// speedup vs baseline: 1.5003x; 1.2277x over previous
#include <cuda_runtime.h>
#include <stdint.h>
#include <math.h>

#define BB 32
#define TT 256
#define INS 64
#define HH 128
#define G4 512
#define EPSV 1e-7f

typedef unsigned long long u64;
typedef unsigned int u32;

// ---- static device scratch (no cudaMalloc allowed) ----
__device__ __align__(16) u64 g_whp[32 * 512 * 2];   // W_hh packed: [k4][j] -> float4 as 2x u64
__device__ float g_gx[BB * TT * G4];                // precomputed input gate contributions

__device__ __forceinline__ u64 ffma2(u64 a, u64 b, u64 c) {
    u64 d;
    asm("fma.rn.f32x2 %0, %1, %2, %3;" : "=l"(d) : "l"(a), "l"(b), "l"(c));
    return d;
}
__device__ __forceinline__ float f2sum(u64 v) {
    float2 f = *reinterpret_cast<float2*>(&v);
    return f.x + f.y;
}
__device__ __forceinline__ float fsig(float x)  { return 1.0f / (1.0f + __expf(-x)); }
__device__ __forceinline__ float ftanh(float x) { return 2.0f / (1.0f + __expf(-2.0f * x)) - 1.0f; }

__device__ __forceinline__ u32 smem_u32(const void* p) {
    u32 a;
    asm("{ .reg .u64 t; cvta.to.shared.u64 t, %1; cvt.u32.u64 %0, t; }" : "=r"(a) : "l"(p));
    return a;
}

__device__ __forceinline__ void mbar_wait_cluster(u32 mb, u32 parity) {
    asm volatile(
        "{\n\t"
        ".reg .pred P;\n\t"
        "WL_%=:\n\t"
        "mbarrier.try_wait.parity.acquire.cluster.shared::cta.b64 P, [%0], %1, 0x989680;\n\t"
        "@P bra.uni WD_%=;\n\t"
        "bra.uni WL_%=;\n\t"
        "WD_%=:\n\t"
        "}"
        :: "r"(mb), "r"(parity) : "memory");
}

// ---------------- fused pack + gx kernel ----------------
__global__ __launch_bounds__(512) void gxpack_kernel(const float* __restrict__ x,
                                                     const float* __restrict__ W_ih,
                                                     const float* __restrict__ W_hh,
                                                     const float* __restrict__ b_ih,
                                                     const float* __restrict__ b_hh) {
    int b = blockIdx.x, ty = blockIdx.y, j = threadIdx.x;

    if (ty == 0) {
        float* whp = (float*)g_whp;
        for (int idx = b * 512 + j; idx < G4 * HH; idx += 32 * 512) {
            int r = idx >> 7, k = idx & 127;
            whp[((k >> 2) * 512 + r) * 4 + (k & 3)] = W_hh[idx];
        }
    }

    __shared__ float xs[16][INS];
    int t0 = ty * 16;
    for (int idx = j; idx < 16 * INS; idx += 512)
        xs[idx >> 6][idx & 63] = x[(b * TT + t0 + (idx >> 6)) * INS + (idx & 63)];

    float4 w[16];
    const float4* wr = (const float4*)(W_ih + j * INS);
#pragma unroll
    for (int k4 = 0; k4 < 16; k4++) w[k4] = wr[k4];
    float bs = b_ih[j] + b_hh[j];
    __syncthreads();

    for (int tt = 0; tt < 16; tt++) {
        float acc = bs;
#pragma unroll
        for (int k4 = 0; k4 < 16; k4++) {
            acc = fmaf(w[k4].x, xs[tt][4 * k4 + 0], acc);
            acc = fmaf(w[k4].y, xs[tt][4 * k4 + 1], acc);
            acc = fmaf(w[k4].z, xs[tt][4 * k4 + 2], acc);
            acc = fmaf(w[k4].w, xs[tt][4 * k4 + 3], acc);
        }
        g_gx[(b * TT + t0 + tt) * G4 + j] = acc;
    }
}

// ---------------- recurrent kernel: cluster of 2 CTAs per batch row ----------------
// 544 threads: warps 0-15 (512 thr) GEMV k-half in registers; warp 16 = scheduler
// (top-5 maintenance + mbarrier expect_tx). Partial exchange via st.async + mbar tx.
__global__ __launch_bounds__(544) void rec_kernel(const float* __restrict__ w_t,
                                                  float* __restrict__ out) {
    int tid = threadIdx.x, lane = tid & 31, wrp = tid >> 5;
    int b = blockIdx.x >> 1;

    u32 rank;
    asm("mov.u32 %0, %%cluster_ctarank;" : "=r"(rank));
    u32 peer = rank ^ 1u;

    __shared__ __align__(16) float h_sh[HH];
    __shared__ float gpart[2][2][G4];              // [parity][khalf][gate]
    __shared__ float pbv[HH];                      // per-h tanh(h)*wb products
    __shared__ __align__(16) float slots[5][HH];   // h rows for running top-5
    __shared__ float redA[4];
    __shared__ float sb_arr[8];                    // only rows 0..4 read
    __shared__ float top5v[5];
    __shared__ int   top5r[5];
    __shared__ int   top5s[5];
    __shared__ int   rowslot[5];
    __shared__ int   evslot;
    __shared__ float wa_s[HH], wb_s[HH];
    __shared__ __align__(8) u64 mbar[2];

    float* out_c = out;             // [B,H]
    float* out_w = out + BB * HH;   // [B,T]
    const float* gxb = g_gx + b * TT * G4;

    if (tid < HH) {
        h_sh[tid] = 0.0f;
        slots[0][tid] = 0.0f;
        wa_s[tid] = w_t[tid];
        wb_s[tid] = w_t[HH + tid];
    }
    if (tid == 0) {
        sb_arr[0] = 0.0f;
        top5v[0] = 0.0f; top5r[0] = 0; top5s[0] = 0;
        for (int q = 1; q < 5; q++) { top5v[q] = -1e30f; top5r[q] = -1; top5s[q] = q; }
        rowslot[0] = 0;
        evslot = -1;
        asm volatile("mbarrier.init.shared.b64 [%0], 1;" :: "r"(smem_u32(&mbar[0])) : "memory");
        asm volatile("mbarrier.init.shared.b64 [%0], 1;" :: "r"(smem_u32(&mbar[1])) : "memory");
    }
    if (rank == 0 && tid < TT) out_w[b * TT + tid] = 0.0f;

    // local + remote (peer) addresses
    u32 mb0 = smem_u32(&mbar[0]);
    u32 mb1 = smem_u32(&mbar[1]);
    u32 gl0 = smem_u32(&gpart[0][rank][0]);
    u32 gl1 = smem_u32(&gpart[1][rank][0]);
    u32 gr0, gr1, rmb0, rmb1;
    asm("mapa.shared::cluster.u32 %0, %1, %2;" : "=r"(gr0)  : "r"(gl0), "r"(peer));
    asm("mapa.shared::cluster.u32 %0, %1, %2;" : "=r"(gr1)  : "r"(gl1), "r"(peer));
    asm("mapa.shared::cluster.u32 %0, %1, %2;" : "=r"(rmb0) : "r"(mb0), "r"(peer));
    asm("mapa.shared::cluster.u32 %0, %1, %2;" : "=r"(rmb1) : "r"(mb1), "r"(peer));

    float c_reg = 0.0f;
    float ac = 0.0f;
    u32 ph0 = 0, ph1 = 0;    // consumer phase per buffer (tail threads only)

    // this CTA's W_hh half: rows = gate j (tid), cols = k in [rank*64, rank*64+64)
    ulonglong2 wc[16];
    if (tid < 512) {
        const ulonglong2* wp = (const ulonglong2*)g_whp;
#pragma unroll
        for (int k4 = 0; k4 < 16; k4++) wc[k4] = wp[(rank * 16 + k4) * 512 + tid];
    }

    __syncthreads();
    // both CTAs fully initialized (incl. mbarriers) before any remote traffic
    asm volatile("barrier.cluster.arrive.aligned;" ::: "memory");
    asm volatile("barrier.cluster.wait.aligned;"   ::: "memory");

    // gx prefetch: only tail threads (tid<128) need gx
    float gx0 = 0.f, gx1 = 0.f, gx2 = 0.f, gx3 = 0.f;
    if (tid < HH) {
        gx0 = gxb[tid];
        gx1 = gxb[HH + tid];
        gx2 = gxb[2 * HH + tid];
        gx3 = gxb[3 * HH + tid];
    }

    for (int i = 0; i < TT; i++) {
        int p = i & 1;

        if (tid < 512) {
            // ---- GEMV half: partial[tid] over this CTA's 64 k's, weights in registers ----
            const ulonglong2* h2 = (const ulonglong2*)h_sh;
            u64 a0 = 0ull, a1 = 0ull, a2 = 0ull, a3 = 0ull;
#pragma unroll
            for (int k4 = 0; k4 < 16; k4++) {
                ulonglong2 w = wc[k4];
                ulonglong2 hv = h2[rank * 16 + k4];
                if (k4 & 1) { a2 = ffma2(w.x, hv.x, a2); a3 = ffma2(w.y, hv.y, a3); }
                else        { a0 = ffma2(w.x, hv.x, a0); a1 = ffma2(w.y, hv.y, a1); }
            }
            float part = (f2sum(a0) + f2sum(a1)) + (f2sum(a2) + f2sum(a3));

            gpart[p][rank][tid] = part;                  // local copy
            u32 ra = (p ? gr1 : gr0) + tid * 4u;         // peer copy w/ tx completion
            u32 rm = p ? rmb1 : rmb0;
            asm volatile(
                "st.async.shared::cluster.mbarrier::complete_tx::bytes.f32 [%0], %1, [%2];"
                :: "r"(ra), "f"(part), "r"(rm) : "memory");
            asm volatile("bar.sync 3, 512;" ::: "memory");  // local partials visible

            if (tid < HH) {
                // wait for peer's 2048 bytes + local expect_tx arrival
                if (p) { mbar_wait_cluster(mb1, ph1); ph1 ^= 1u; }
                else   { mbar_wait_cluster(mb0, ph0); ph0 ^= 1u; }
                asm volatile("bar.sync 2, 160;" ::: "memory");  // phase-A results ready

                // gates
                float ti = fsig (gpart[p][0][tid]          + gpart[p][1][tid]          + gx0);
                float tf = fsig (gpart[p][0][HH + tid]     + gpart[p][1][HH + tid]     + gx1);
                float tg = ftanh(gpart[p][0][2 * HH + tid] + gpart[p][1][2 * HH + tid] + gx2);
                float to = fsig (gpart[p][0][3 * HH + tid] + gpart[p][1][3 * HH + tid] + gx3);

                // prefetch next step's gx (L1-resident now: no per-step flush)
                if (i + 1 < TT) {
                    const float* gn = gxb + (i + 1) * G4;
                    gx0 = gn[tid]; gx1 = gn[HH + tid]; gx2 = gn[2 * HH + tid]; gx3 = gn[3 * HH + tid];
                }

                // slot insert (previous h = row i) + LSTM cell + ta partials
                int ev = evslot;
                if (ev >= 0) slots[ev][tid] = h_sh[tid];
                c_reg = tf * c_reg + ti * tg;
                float hl = to * ftanh(c_reg);
                float pa = ftanh(hl) * wa_s[tid];
#pragma unroll
                for (int o = 16; o; o >>= 1) pa += __shfl_xor_sync(0xffffffffu, pa, o);
                if (lane == 0) redA[wrp] = pa;
                asm volatile("bar.sync 1, 128;" ::: "memory");

                // sparse attention (redundant on 128 threads) + h update
                float ta = redA[0] + redA[1] + redA[2] + redA[3];
                int rem = i + 1;
                float wv[5]; int ws[5];
                if (rem <= 5) {
#pragma unroll
                    for (int r = 0; r < 5; r++) {
                        if (r < rem) { wv[r] = ta + sb_arr[r]; ws[r] = rowslot[r]; }
                        else         { wv[r] = 0.0f;           ws[r] = 0; }
                    }
                } else {
                    float d = top5v[4] + EPSV;
                    float ssum = 0.0f;
#pragma unroll
                    for (int q = 0; q < 5; q++) {
                        float v = fmaxf(top5v[q] - d, 0.0f);
                        wv[q] = v; ws[q] = top5s[q];
                        ssum += v;
                    }
                    float inv = 1.0f / (ssum + EPSV);
#pragma unroll
                    for (int q = 0; q < 5; q++) wv[q] *= inv;
                }
                ac = 0.0f;
#pragma unroll
                for (int q = 0; q < 5; q++) ac = fmaf(wv[q], slots[ws[q]][tid], ac);
                float hf = hl + ac;
                h_sh[tid] = hf;
                pbv[tid] = ftanh(hf) * wb_s[tid];   // reduced by warp 16 next step
            }
        } else {
            // ---- warp 16: expect_tx + top-5 maintenance (overlaps GEMV) ----
            if (lane == 0) {
                u32 mb = p ? mb1 : mb0;
                asm volatile("mbarrier.arrive.expect_tx.shared.b64 _, [%0], %1;"
                             :: "r"(mb), "r"(2048u) : "memory");
            }
            if (i > 0) {
                float s = pbv[lane] + pbv[lane + 32] + pbv[lane + 64] + pbv[lane + 96];
#pragma unroll
                for (int o = 16; o; o >>= 1) s += __shfl_xor_sync(0xffffffffu, s, o);
                if (lane == 0) {
                    float sbn = s;
                    if (i < 5) sb_arr[i] = sbn;
                    if (sbn > top5v[4]) {
                        int evs = top5s[4];
                        int q = 4;
                        while (q > 0 && sbn > top5v[q - 1]) {
                            top5v[q] = top5v[q - 1]; top5r[q] = top5r[q - 1]; top5s[q] = top5s[q - 1];
                            q--;
                        }
                        top5v[q] = sbn; top5r[q] = i; top5s[q] = evs;
                        if (i < 5) rowslot[i] = evs;
                        evslot = evs;
                    } else evslot = -1;
                }
            }
            asm volatile("bar.sync 2, 160;" ::: "memory");
        }
        __syncthreads();  // step boundary: h_sh/pbv stable for next step
    }

    // ---- epilogue (rank 0 only) ----
    if (rank == 0) {
        if (tid < HH) out_c[b * HH + tid] = ac;
        if (tid == 0) {
            float d = top5v[4] + EPSV;
            float ssum = 0.0f, v[5];
#pragma unroll
            for (int q = 0; q < 5; q++) { v[q] = fmaxf(top5v[q] - d, 0.0f); ssum += v[q]; }
            float inv = 1.0f / (ssum + EPSV);
#pragma unroll
            for (int q = 0; q < 5; q++)
                if (v[q] > 0.0f) out_w[b * TT + top5r[q]] = v[q] * inv;
        }
    }
    // no CTA exits while peer traffic may be in flight
    asm volatile("barrier.cluster.arrive.aligned;" ::: "memory");
    asm volatile("barrier.cluster.wait.aligned;"   ::: "memory");
}

extern "C" void kernel_launch(void* const* d_in, const int* in_sizes, int n_in,
                              void* d_out, int out_size) {
    const float* x    = (const float*)d_in[0];
    const float* W_ih = (const float*)d_in[1];
    const float* W_hh = (const float*)d_in[2];
    const float* b_ih = (const float*)d_in[3];
    const float* b_hh = (const float*)d_in[4];
    const float* w_t  = (const float*)d_in[5];
    float* out = (float*)d_out;

    gxpack_kernel<<<dim3(BB, TT / 16), 512>>>(x, W_ih, W_hh, b_ih, b_hh);

    cudaLaunchConfig_t cfg = {};
    cfg.gridDim  = dim3(2 * BB, 1, 1);
    cfg.blockDim = dim3(544, 1, 1);
    cfg.dynamicSmemBytes = 0;
    cfg.stream = 0;
    cudaLaunchAttribute attrs[1];
    attrs[0].id = cudaLaunchAttributeClusterDimension;
    attrs[0].val.clusterDim.x = 2;
    attrs[0].val.clusterDim.y = 1;
    attrs[0].val.clusterDim.z = 1;
    cfg.attrs = attrs;
    cfg.numAttrs = 1;
    cudaLaunchKernelEx(&cfg, rec_kernel, w_t, out);
}

// round 8
// speedup vs baseline: 1.5665x; 1.0441x over previous
#include <cuda_runtime.h>
#include <stdint.h>
#include <math.h>

#define BB 32
#define TT 256
#define INS 64
#define HH 128
#define G4 512
#define EPSV 1e-7f

typedef unsigned long long u64;
typedef unsigned int u32;

// ---- static device scratch (no cudaMalloc allowed) ----
__device__ __align__(16) u64 g_whp[32 * 512 * 2];   // W_hh packed: [k4][j] -> float4 as 2x u64
__device__ float g_gx[BB * TT * G4];                // precomputed input gate contributions

__device__ __forceinline__ u64 ffma2(u64 a, u64 b, u64 c) {
    u64 d;
    asm("fma.rn.f32x2 %0, %1, %2, %3;" : "=l"(d) : "l"(a), "l"(b), "l"(c));
    return d;
}
__device__ __forceinline__ float f2sum(u64 v) {
    float2 f = *reinterpret_cast<float2*>(&v);
    return f.x + f.y;
}
__device__ __forceinline__ float fsig(float x)  { return 1.0f / (1.0f + __expf(-x)); }
__device__ __forceinline__ float ftanh(float x) { return 2.0f / (1.0f + __expf(-2.0f * x)) - 1.0f; }

__device__ __forceinline__ u32 smem_u32(const void* p) {
    u32 a;
    asm("{ .reg .u64 t; cvta.to.shared.u64 t, %1; cvt.u32.u64 %0, t; }" : "=r"(a) : "l"(p));
    return a;
}

__device__ __forceinline__ void mbar_wait_cluster(u32 mb, u32 parity) {
    asm volatile(
        "{\n\t"
        ".reg .pred P;\n\t"
        "WL_%=:\n\t"
        "mbarrier.try_wait.parity.acquire.cluster.shared::cta.b64 P, [%0], %1, 0x989680;\n\t"
        "@P bra.uni WD_%=;\n\t"
        "bra.uni WL_%=;\n\t"
        "WD_%=:\n\t"
        "}"
        :: "r"(mb), "r"(parity) : "memory");
}

// ---------------- fused pack + gx kernel ----------------
__global__ __launch_bounds__(512) void gxpack_kernel(const float* __restrict__ x,
                                                     const float* __restrict__ W_ih,
                                                     const float* __restrict__ W_hh,
                                                     const float* __restrict__ b_ih,
                                                     const float* __restrict__ b_hh) {
    int b = blockIdx.x, ty = blockIdx.y, j = threadIdx.x;

    if (ty == 0) {
        float* whp = (float*)g_whp;
        for (int idx = b * 512 + j; idx < G4 * HH; idx += 32 * 512) {
            int r = idx >> 7, k = idx & 127;
            whp[((k >> 2) * 512 + r) * 4 + (k & 3)] = W_hh[idx];
        }
    }

    __shared__ float xs[16][INS];
    int t0 = ty * 16;
    for (int idx = j; idx < 16 * INS; idx += 512)
        xs[idx >> 6][idx & 63] = x[(b * TT + t0 + (idx >> 6)) * INS + (idx & 63)];

    float4 w[16];
    const float4* wr = (const float4*)(W_ih + j * INS);
#pragma unroll
    for (int k4 = 0; k4 < 16; k4++) w[k4] = wr[k4];
    float bs = b_ih[j] + b_hh[j];
    __syncthreads();

    for (int tt = 0; tt < 16; tt++) {
        float acc = bs;
#pragma unroll
        for (int k4 = 0; k4 < 16; k4++) {
            acc = fmaf(w[k4].x, xs[tt][4 * k4 + 0], acc);
            acc = fmaf(w[k4].y, xs[tt][4 * k4 + 1], acc);
            acc = fmaf(w[k4].z, xs[tt][4 * k4 + 2], acc);
            acc = fmaf(w[k4].w, xs[tt][4 * k4 + 3], acc);
        }
        g_gx[(b * TT + t0 + tt) * G4 + j] = acc;
    }
}

// ---------------- recurrent kernel: cluster of 2 CTAs per batch row ----------------
// 544 threads: warps 0-15 GEMV k-half (weights in registers, rank0 folds gx in);
// warp 16 = scheduler (top-5 + expect_tx). All partials (local+peer) delivered via
// st.async with tx accounting on one mbarrier per parity: zero GEMV-side barriers.
__global__ __launch_bounds__(544) void rec_kernel(const float* __restrict__ w_t,
                                                  float* __restrict__ out) {
    int tid = threadIdx.x, lane = tid & 31, wrp = tid >> 5;
    int b = blockIdx.x >> 1;

    u32 rank;
    asm("mov.u32 %0, %%cluster_ctarank;" : "=r"(rank));
    u32 peer = rank ^ 1u;

    __shared__ __align__(16) float h_sh[HH];
    __shared__ float gpart[2][2][G4];              // [parity][khalf][gate]
    __shared__ float pbv[HH];                      // per-h tanh(h)*wb products
    __shared__ __align__(16) float slots[5][HH];   // h rows for running top-5
    __shared__ float redA[4];
    __shared__ float sb_arr[8];                    // only rows 0..4 read
    __shared__ float top5v[5];
    __shared__ int   top5r[5];
    __shared__ int   top5s[5];
    __shared__ int   rowslot[5];
    __shared__ int   evslot;
    __shared__ float wa_s[HH], wb_s[HH];
    __shared__ __align__(8) u64 mbar[2];

    float* out_c = out;             // [B,H]
    float* out_w = out + BB * HH;   // [B,T]
    const float* gxb = g_gx + b * TT * G4;

    if (tid < HH) {
        h_sh[tid] = 0.0f;
        slots[0][tid] = 0.0f;
        wa_s[tid] = w_t[tid];
        wb_s[tid] = w_t[HH + tid];
    }
    if (tid == 0) {
        sb_arr[0] = 0.0f;
        top5v[0] = 0.0f; top5r[0] = 0; top5s[0] = 0;
        for (int q = 1; q < 5; q++) { top5v[q] = -1e30f; top5r[q] = -1; top5s[q] = q; }
        rowslot[0] = 0;
        evslot = -1;
        asm volatile("mbarrier.init.shared.b64 [%0], 1;" :: "r"(smem_u32(&mbar[0])) : "memory");
        asm volatile("mbarrier.init.shared.b64 [%0], 1;" :: "r"(smem_u32(&mbar[1])) : "memory");
    }
    if (rank == 0 && tid < TT) out_w[b * TT + tid] = 0.0f;

    // cluster-space addresses: own buffers (for local st.async) + peer buffers
    u32 mb0 = smem_u32(&mbar[0]);
    u32 mb1 = smem_u32(&mbar[1]);
    u32 gl0 = smem_u32(&gpart[0][rank][0]);
    u32 gl1 = smem_u32(&gpart[1][rank][0]);
    u32 sl0, sl1, smb0, smb1, gr0, gr1, rmb0, rmb1;
    asm("mapa.shared::cluster.u32 %0, %1, %2;" : "=r"(sl0)  : "r"(gl0), "r"(rank));
    asm("mapa.shared::cluster.u32 %0, %1, %2;" : "=r"(sl1)  : "r"(gl1), "r"(rank));
    asm("mapa.shared::cluster.u32 %0, %1, %2;" : "=r"(smb0) : "r"(mb0), "r"(rank));
    asm("mapa.shared::cluster.u32 %0, %1, %2;" : "=r"(smb1) : "r"(mb1), "r"(rank));
    asm("mapa.shared::cluster.u32 %0, %1, %2;" : "=r"(gr0)  : "r"(gl0), "r"(peer));
    asm("mapa.shared::cluster.u32 %0, %1, %2;" : "=r"(gr1)  : "r"(gl1), "r"(peer));
    asm("mapa.shared::cluster.u32 %0, %1, %2;" : "=r"(rmb0) : "r"(mb0), "r"(peer));
    asm("mapa.shared::cluster.u32 %0, %1, %2;" : "=r"(rmb1) : "r"(mb1), "r"(peer));

    float c_reg = 0.0f;
    float ac = 0.0f;
    u32 ph0 = 0, ph1 = 0;

    // this CTA's W_hh half: rows = gate j (tid), cols = k in [rank*64, rank*64+64)
    ulonglong2 wc[16];
    float gxv = 0.0f;
    if (tid < 512) {
        const ulonglong2* wp = (const ulonglong2*)g_whp;
#pragma unroll
        for (int k4 = 0; k4 < 16; k4++) wc[k4] = wp[(rank * 16 + k4) * 512 + tid];
        if (rank == 0) gxv = gxb[tid];   // gx folded into rank-0 partial
    }

    __syncthreads();
    asm volatile("barrier.cluster.arrive.aligned;" ::: "memory");
    asm volatile("barrier.cluster.wait.aligned;"   ::: "memory");

    for (int i = 0; i < TT; i++) {
        int p = i & 1;

        if (tid < 512) {
            // ---- GEMV half (register weights); rank 0 adds gx ----
            const ulonglong2* h2 = (const ulonglong2*)h_sh;
            u64 a0 = 0ull, a1 = 0ull, a2 = 0ull, a3 = 0ull;
#pragma unroll
            for (int k4 = 0; k4 < 16; k4++) {
                ulonglong2 w = wc[k4];
                ulonglong2 hv = h2[rank * 16 + k4];
                if (k4 & 1) { a2 = ffma2(w.x, hv.x, a2); a3 = ffma2(w.y, hv.y, a3); }
                else        { a0 = ffma2(w.x, hv.x, a0); a1 = ffma2(w.y, hv.y, a1); }
            }
            float part = gxv + (f2sum(a0) + f2sum(a1)) + (f2sum(a2) + f2sum(a3));
            if (rank == 0 && i + 1 < TT) gxv = gxb[(i + 1) * G4 + tid];  // prefetch

            // local + remote delivery, both tx-counted on destination CTA's mbar[p]
            u32 la = (p ? sl1 : sl0) + tid * 4u;
            u32 lm = p ? smb1 : smb0;
            u32 ra = (p ? gr1 : gr0) + tid * 4u;
            u32 rm = p ? rmb1 : rmb0;
            asm volatile("st.async.shared::cluster.mbarrier::complete_tx::bytes.f32 [%0], %1, [%2];"
                         :: "r"(la), "f"(part), "r"(lm) : "memory");
            asm volatile("st.async.shared::cluster.mbarrier::complete_tx::bytes.f32 [%0], %1, [%2];"
                         :: "r"(ra), "f"(part), "r"(rm) : "memory");

            if (tid < HH) {
                // overlap DSMEM RTT: sync with scheduler warp, insert evicted slot
                asm volatile("bar.sync 2, 160;" ::: "memory");
                int ev = evslot;
                if (ev >= 0) slots[ev][tid] = h_sh[tid];   // row i = h(i-1)

                // wait for all 4096 bytes of partials
                if (p) { mbar_wait_cluster(mb1, ph1); ph1 ^= 1u; }
                else   { mbar_wait_cluster(mb0, ph0); ph0 ^= 1u; }

                // gates
                float ti = fsig (gpart[p][0][tid]          + gpart[p][1][tid]);
                float tf = fsig (gpart[p][0][HH + tid]     + gpart[p][1][HH + tid]);
                float tg = ftanh(gpart[p][0][2 * HH + tid] + gpart[p][1][2 * HH + tid]);
                float to = fsig (gpart[p][0][3 * HH + tid] + gpart[p][1][3 * HH + tid]);
                c_reg = tf * c_reg + ti * tg;
                float hl = to * ftanh(c_reg);

                float wv[5]; int ws[5];
                if (i < 5) {
                    // ta needed only while rem<=5 (raw unnormalized scores)
                    float pa = ftanh(hl) * wa_s[tid];
#pragma unroll
                    for (int o = 16; o; o >>= 1) pa += __shfl_xor_sync(0xffffffffu, pa, o);
                    if (lane == 0) redA[wrp] = pa;
                    asm volatile("bar.sync 1, 128;" ::: "memory");
                    float ta = redA[0] + redA[1] + redA[2] + redA[3];
                    int rem = i + 1;
#pragma unroll
                    for (int r = 0; r < 5; r++) {
                        if (r < rem) { wv[r] = ta + sb_arr[r]; ws[r] = rowslot[r]; }
                        else         { wv[r] = 0.0f;           ws[r] = 0; }
                    }
                } else {
                    // ta cancels in the clipped-sparse path
                    float d = top5v[4] + EPSV;
                    float ssum = 0.0f;
#pragma unroll
                    for (int q = 0; q < 5; q++) {
                        float v = fmaxf(top5v[q] - d, 0.0f);
                        wv[q] = v; ws[q] = top5s[q];
                        ssum += v;
                    }
                    float inv = 1.0f / (ssum + EPSV);
#pragma unroll
                    for (int q = 0; q < 5; q++) wv[q] *= inv;
                }
                ac = 0.0f;
#pragma unroll
                for (int q = 0; q < 5; q++) ac = fmaf(wv[q], slots[ws[q]][tid], ac);
                float hf = hl + ac;
                h_sh[tid] = hf;
                pbv[tid] = ftanh(hf) * wb_s[tid];   // reduced by warp 16 next step
            }
        } else {
            // ---- warp 16: expect_tx + top-5 maintenance (overlaps GEMV) ----
            if (lane == 0) {
                u32 mb = p ? mb1 : mb0;
                asm volatile("mbarrier.arrive.expect_tx.shared.b64 _, [%0], %1;"
                             :: "r"(mb), "r"(4096u) : "memory");
            }
            if (i > 0) {
                float s = pbv[lane] + pbv[lane + 32] + pbv[lane + 64] + pbv[lane + 96];
#pragma unroll
                for (int o = 16; o; o >>= 1) s += __shfl_xor_sync(0xffffffffu, s, o);
                if (lane == 0) {
                    float sbn = s;
                    if (i < 5) sb_arr[i] = sbn;
                    if (sbn > top5v[4]) {
                        int evs = top5s[4];
                        int q = 4;
                        while (q > 0 && sbn > top5v[q - 1]) {
                            top5v[q] = top5v[q - 1]; top5r[q] = top5r[q - 1]; top5s[q] = top5s[q - 1];
                            q--;
                        }
                        top5v[q] = sbn; top5r[q] = i; top5s[q] = evs;
                        if (i < 5) rowslot[i] = evs;
                        evslot = evs;
                    } else evslot = -1;
                }
            }
            asm volatile("bar.sync 2, 160;" ::: "memory");
        }
        __syncthreads();  // step boundary: h_sh/pbv stable for next step
    }

    // ---- epilogue (rank 0 only) ----
    if (rank == 0) {
        if (tid < HH) out_c[b * HH + tid] = ac;
        if (tid == 0) {
            float d = top5v[4] + EPSV;
            float ssum = 0.0f, v[5];
#pragma unroll
            for (int q = 0; q < 5; q++) { v[q] = fmaxf(top5v[q] - d, 0.0f); ssum += v[q]; }
            float inv = 1.0f / (ssum + EPSV);
#pragma unroll
            for (int q = 0; q < 5; q++)
                if (v[q] > 0.0f) out_w[b * TT + top5r[q]] = v[q] * inv;
        }
    }
    asm volatile("barrier.cluster.arrive.aligned;" ::: "memory");
    asm volatile("barrier.cluster.wait.aligned;"   ::: "memory");
}

extern "C" void kernel_launch(void* const* d_in, const int* in_sizes, int n_in,
                              void* d_out, int out_size) {
    const float* x    = (const float*)d_in[0];
    const float* W_ih = (const float*)d_in[1];
    const float* W_hh = (const float*)d_in[2];
    const float* b_ih = (const float*)d_in[3];
    const float* b_hh = (const float*)d_in[4];
    const float* w_t  = (const float*)d_in[5];
    float* out = (float*)d_out;

    gxpack_kernel<<<dim3(BB, TT / 16), 512>>>(x, W_ih, W_hh, b_ih, b_hh);

    cudaLaunchConfig_t cfg = {};
    cfg.gridDim  = dim3(2 * BB, 1, 1);
    cfg.blockDim = dim3(544, 1, 1);
    cfg.dynamicSmemBytes = 0;
    cfg.stream = 0;
    cudaLaunchAttribute attrs[1];
    attrs[0].id = cudaLaunchAttributeClusterDimension;
    attrs[0].val.clusterDim.x = 2;
    attrs[0].val.clusterDim.y = 1;
    attrs[0].val.clusterDim.z = 1;
    cfg.attrs = attrs;
    cfg.numAttrs = 1;
    cudaLaunchKernelEx(&cfg, rec_kernel, w_t, out);
}